// round 13
// baseline (speedup 1.0000x reference)
#include <cuda_runtime.h>
#include <math.h>
#include <stdint.h>

#define BQ    16
#define SEQ   512
#define NFch  32
#define ECH   128
#define HID   512
#define PRED  96
#define NFFT  64
#define HOPL  32
#define TOPM  32
#define WN    17
#define FB    33
#define LAMB  0.01f

#define ROWS  (BQ*NFch)      // 512  (b*32+n)
#define KTOT  (SEQ*ECH)      // 65536
#define KSPLIT 32
#define KCHUNK (KTOT/KSPLIT) // 2048
#define BK    32
#define NSTAGE (KCHUNK/BK)   // 64
#define EH    64             // e-channels per k_main CTA (e-split)

// ---------------- scratch (static device globals; no runtime alloc) --------
__device__ float2 g_c[ROWS*WN*TOPM];
__device__ int    g_fidx[ROWS*WN*TOPM];
__device__ float  g_v[6*WN*ECH];
__device__ float  g_xo[(size_t)ROWS*KTOT];          // tf32-rounded, ~134MB
__device__ float  g_Hpart[(size_t)KSPLIT*ROWS*HID];

#define TWO_PI 6.28318530717958647692f
#define TWO_PI_D 6.28318530717958647692528676655900577

__device__ __forceinline__ int reflect_t(int j) {
    int t = j - 32;
    if (t < 0) t = -t;
    else if (t > SEQ-1) t = 2*(SEQ-1) - t;
    return t;
}

__device__ __forceinline__ uint32_t f2tf32u(float f) {
    uint32_t r; asm("cvt.rna.tf32.f32 %0, %1;" : "=r"(r) : "f"(f)); return r;
}

__device__ __forceinline__ void mma_tf32(float* c, const uint32_t* a, const uint32_t* b) {
    asm volatile("mma.sync.aligned.m16n8k8.row.col.f32.tf32.tf32.f32 "
        "{%0,%1,%2,%3}, {%4,%5,%6,%7}, {%8,%9}, {%0,%1,%2,%3};"
        : "+f"(c[0]), "+f"(c[1]), "+f"(c[2]), "+f"(c[3])
        : "r"(a[0]), "r"(a[1]), "r"(a[2]), "r"(a[3]), "r"(b[0]), "r"(b[1]));
}

__device__ __forceinline__ uint32_t smem_u32(const void* p) {
    uint32_t a;
    asm("{ .reg .u64 t; cvta.to.shared.u64 t, %1; cvt.u32.u64 %0, t; }" : "=r"(a) : "l"(p));
    return a;
}
__device__ __forceinline__ void cp16(uint32_t dst, const void* src) {
    asm volatile("cp.async.ca.shared.global [%0], [%1], 16;" :: "r"(dst), "l"(src));
}

// packed f32x2 helpers (Blackwell FFMA2; IEEE fp32 per lane)
__device__ __forceinline__ void fma2(unsigned long long& acc, unsigned long long a, unsigned long long b) {
    asm("fma.rn.f32x2 %0, %1, %2, %0;" : "+l"(acc) : "l"(a), "l"(b));
}
__device__ __forceinline__ unsigned long long pack2(float lo, float hi) {
    unsigned long long r; asm("mov.b64 %0, {%1, %2};" : "=l"(r) : "f"(lo), "f"(hi)); return r;
}
__device__ __forceinline__ void unpack2(float& lo, float& hi, unsigned long long v) {
    asm("mov.b64 {%0, %1}, %2;" : "=f"(lo), "=f"(hi) : "l"(v));
}

// ---------------- Kernel A: STFT (df64 fp32, exact twiddles) + top-32 ------
__global__ void k_stft(const float* __restrict__ x) {
    __shared__ float s_s[SEQ];
    __shared__ float win_s[NFFT];
    __shared__ float chi_s[NFFT], clo_s[NFFT];
    __shared__ float mhi_s[NFFT], mlo_s[NFFT];
    __shared__ float Sre[WN*FB], Sim[WN*FB], Sab[WN*FB];
    int blk = blockIdx.x;
    int b = blk >> 5, n = blk & 31;
    int tid = threadIdx.x;          // 128

    for (int t = tid; t < SEQ; t += 128) s_s[t] = x[(b*SEQ + t)*NFch + n];
    for (int t = tid; t < NFFT; t += 128) {
        float a = TWO_PI * (float)t / (float)NFFT;
        win_s[t] = 0.5f - 0.5f * (float)cos((double)a);
        double ad = TWO_PI_D * (double)t / 64.0;
        double cd = cos(ad), msd = -sin(ad);
        float ch = (float)cd;  chi_s[t] = ch; clo_s[t] = (float)(cd - (double)ch);
        float mh = (float)msd; mhi_s[t] = mh; mlo_s[t] = (float)(msd - (double)mh);
    }
    __syncthreads();

    for (int task = tid; task < WN*FB; task += 128) {
        int w = task / FB, f = task % FB;
        float rh = 0.f, rl = 0.f, ih = 0.f, il = 0.f;
        for (int k = 0; k < NFFT; k++) {
            float v = s_s[reflect_t(w*HOPL + k)] * win_s[k];
            int a = (f*k) & 63;
            float ch = chi_s[a];
            float ph = v * ch;
            float pe = fmaf(v, ch, -ph);
            pe = fmaf(v, clo_s[a], pe);
            float s  = rh + ph;
            float bb = s - rh;
            float er = (rh - (s - bb)) + (ph - bb);
            rh = s; rl += er + pe;
            float mh = mhi_s[a];
            float qh = v * mh;
            float qe = fmaf(v, mh, -qh);
            qe = fmaf(v, mlo_s[a], qe);
            float s2  = ih + qh;
            float b2  = s2 - ih;
            float e2  = (ih - (s2 - b2)) + (qh - b2);
            ih = s2; il += e2 + qe;
        }
        float rf = rh + rl, imf = ih + il;
        Sre[task] = rf; Sim[task] = imf;
        Sab[task] = (float)sqrt((double)rf*rf + (double)imf*imf);
    }
    __syncthreads();

    if (tid < WN) {
        int w = tid;
        float mag[FB]; bool used[FB];
        for (int f = 0; f < FB; f++) { mag[f] = Sab[w*FB+f]; used[f] = false; }
        int base = (blk*WN + w) * TOPM;
        for (int m = 0; m < TOPM; m++) {
            int best = 0; float bv = -1.f;
            for (int f = 0; f < FB; f++)
                if (!used[f] && mag[f] > bv) { bv = mag[f]; best = f; }
            used[best] = true;
            g_fidx[base+m] = best;
            g_c[base+m] = make_float2(Sre[w*FB+best], Sim[w*FB+best]);
        }
    }
}

// ---------------- Kernel B: v[k][w][f] = sum_e emb[e]*Wk[w,e,f] ------------
__global__ void k_vred(const float* __restrict__ emb,
                       const float* __restrict__ Wr,  const float* __restrict__ Wi,
                       const float* __restrict__ Wrl, const float* __restrict__ Wil,
                       const float* __restrict__ Wrr, const float* __restrict__ Wir) {
    int k = blockIdx.x / WN, w = blockIdx.x % WN;
    const float* Wm = (k==0)?Wr:(k==1)?Wi:(k==2)?Wrl:(k==3)?Wil:(k==4)?Wrr:Wir;
    int f = threadIdx.x;
    const float* base = Wm + (size_t)w*ECH*ECH + f;
    float acc = 0.f;
    #pragma unroll 4
    for (int e = 0; e < ECH; e++) acc = fmaf(emb[e], base[(size_t)e*ECH], acc);
    g_v[(k*WN + w)*ECH + f] = acc;
}

// ---------------- Kernel C: e-split fused Y + parity irfft + OLA + bias ----
#define SMEM_MAIN 43008
__global__ __launch_bounds__(256, 4) void k_main(
        const float* __restrict__ x, const float* __restrict__ emb,
        const float* __restrict__ br, const float* __restrict__ bi) {
    extern __shared__ char smraw[];
    ulonglong2* tw64 = (ulonglong2*)(smraw);
    float*  y_re   = (float*) (smraw + 1024);
    float*  y_im   = (float*) (smraw + 9216);
    float*  ring   = (float*) (smraw + 17408);
    float2* cc     = (float2*)(smraw + 33792);
    float*  vs     = (float*) (smraw + 38144);
    float*  win_s  = (float*) (smraw + 40192);
    float*  ienv   = (float*) (smraw + 40448);
    float*  emb_s  = (float*) (smraw + 40576);
    int*    fidx_s = (int*)   (smraw + 40832);

    int tid = threadIdx.x;          // 256
    int bx  = blockIdx.x;
    int blk = bx >> 1, half = bx & 1;
    int e_off = half * EH;
    int b = blk >> 5, n = blk & 31;

    for (int i = tid; i < 64; i += 256) {
        double ad = TWO_PI_D * (double)i / 64.0;
        float c = (float)cos(ad), s = (float)sin(ad);
        ulonglong2 v; v.x = pack2(c, c); v.y = pack2(-s, -s);
        tw64[i] = v;
    }
    for (int i = tid; i < NFFT; i += 256) {
        float a = TWO_PI * (float)i / (float)NFFT;
        win_s[i] = 0.5f - 0.5f * (float)cos((double)a);
    }
    for (int i = tid; i < HOPL; i += 256) {
        float a = TWO_PI * (float)i / (float)NFFT;
        float c = (float)cos((double)a);
        float w0 = 0.5f - 0.5f*c, w1 = 0.5f + 0.5f*c;
        ienv[i] = 1.0f / (w0*w0 + w1*w1);
    }
    for (int i = tid; i < EH; i += 256) emb_s[i] = emb[e_off + i];
    for (int i = tid; i < WN*TOPM; i += 256) {
        cc[i]     = g_c[blk*WN*TOPM + i];
        fidx_s[i] = g_fidx[blk*WN*TOPM + i];
    }
    __syncthreads();

    int lane = tid & 31, wid = tid >> 5;
    int e0l = (lane & 15) << 2;                 // local e 0..60 (quad)
    int t0  = wid*4 + ((lane >> 4) << 1);       // base t 0..30 (pair)

    for (int w = 0; w < WN; w++) {
        for (int i = tid; i < 8*EH; i += 256) {
            int k = i >> 6, e = i & 63;
            float v;
            if (k < 6)      v = g_v[(k*WN + w)*ECH + e_off + e];
            else if (k == 6) v = br[w*ECH + e_off + e];
            else             v = bi[w*ECH + e_off + e];
            vs[i] = v;
        }
        __syncthreads();

        for (int i = tid; i < EH*TOPM; i += 256) {
            int m = i >> 6, e = i & 63;
            float2 c0 = cc[w*TOPM + m];
            float2 cl = (w > 0)    ? cc[(w-1)*TOPM + m] : make_float2(0.f,0.f);
            float2 cr = (w < WN-1) ? cc[(w+1)*TOPM + m] : make_float2(0.f,0.f);
            float vr  = vs[e],       vi  = vs[EH+e];
            float vrl = vs[2*EH+e],  vil = vs[3*EH+e];
            float vrr = vs[4*EH+e],  vir = vs[5*EH+e];
            float ore = c0.x*vr - c0.y*vi + cl.x*vrl - cl.y*vil + cr.x*vrr - cr.y*vir + vs[6*EH+e];
            float oim = c0.y*vr + c0.x*vi + cl.y*vrl + cl.x*vil + cr.y*vrr + cr.x*vir + vs[7*EH+e];
            float yre = fmaxf(fmaxf(ore, 0.f) - LAMB, 0.f);
            float yim = fmaxf(fmaxf(oim, 0.f) - LAMB, 0.f);
            int f = fidx_s[w*TOPM + m];
            if (f == 0 || f == FB-1) {
                y_re[i] = yre * 0.015625f;
                y_im[i] = 0.f;
            } else {
                y_re[i] = yre * 0.03125f;
                y_im[i] = yim * 0.03125f;
            }
        }
        __syncthreads();

        unsigned long long aE[2][2], aO[2][2];
        #pragma unroll
        for (int kk = 0; kk < 2; kk++) {
            aE[kk][0] = aE[kk][1] = 0ull;
            aO[kk][0] = aO[kk][1] = 0ull;
        }

        #pragma unroll 4
        for (int m = 0; m < TOPM; m++) {
            int f = fidx_s[w*TOPM + m];
            ulonglong2 yr = *(const ulonglong2*)&y_re[m*EH + e0l];
            ulonglong2 yi = *(const ulonglong2*)&y_im[m*EH + e0l];
            int ft = f * t0;
            ulonglong2 cs0 = tw64[ft & 63];
            ulonglong2 cs1 = tw64[(ft + f) & 63];
            if (f & 1) {
                fma2(aO[0][0], yr.x, cs0.x); fma2(aO[0][0], yi.x, cs0.y);
                fma2(aO[0][1], yr.y, cs0.x); fma2(aO[0][1], yi.y, cs0.y);
                fma2(aO[1][0], yr.x, cs1.x); fma2(aO[1][0], yi.x, cs1.y);
                fma2(aO[1][1], yr.y, cs1.x); fma2(aO[1][1], yi.y, cs1.y);
            } else {
                fma2(aE[0][0], yr.x, cs0.x); fma2(aE[0][0], yi.x, cs0.y);
                fma2(aE[0][1], yr.y, cs0.x); fma2(aE[0][1], yi.y, cs0.y);
                fma2(aE[1][0], yr.x, cs1.x); fma2(aE[1][0], yi.x, cs1.y);
                fma2(aE[1][1], yr.y, cs1.x); fma2(aE[1][1], yi.y, cs1.y);
            }
        }

        #pragma unroll
        for (int kk = 0; kk < 2; kk++) {
            int t  = t0 + kk;
            int tm = t + 32;
            float pe0, pe1, pe2, pe3, po0, po1, po2, po3;
            unpack2(pe0, pe1, aE[kk][0]); unpack2(pe2, pe3, aE[kk][1]);
            unpack2(po0, po1, aO[kk][0]); unpack2(po2, po3, aO[kk][1]);

            float wt = win_s[t], wmr = win_s[tm];
            int slot_t = (w*HOPL + t)  & 63;
            int slot_m = (w*HOPL + tm) & 63;

            float4 vt, vm;
            vt.x = (pe0+po0)*wt;  vt.y = (pe1+po1)*wt;
            vt.z = (pe2+po2)*wt;  vt.w = (pe3+po3)*wt;
            vm.x = (pe0-po0)*wmr; vm.y = (pe1-po1)*wmr;
            vm.z = (pe2-po2)*wmr; vm.w = (pe3-po3)*wmr;

            float4* rpt = (float4*)&ring[slot_t*EH + e0l];
            if (w > 0) {
                float4 o = *rpt;
                vt.x += o.x; vt.y += o.y; vt.z += o.z; vt.w += o.w;
            }
            *rpt = vt;
            *(float4*)&ring[slot_m*EH + e0l] = vm;
        }
        __syncthreads();

        if (w > 0) {
            for (int i = tid; i < HOPL*EH; i += 256) {
                int r = i >> 6, e = i & 63;
                int t_out = (w-1)*HOPL + r;
                int slot = (w*HOPL + r) & 63;
                float val = ring[slot*EH + e] * ienv[r]
                          + x[(b*SEQ + t_out)*NFch + n] * emb_s[e];
                g_xo[(size_t)blk*KTOT + t_out*ECH + e_off + e] = __uint_as_float(f2tf32u(val));
            }
        }
        __syncthreads();
    }
}

// ---------------- Kernel D: FC1 split-K, 1xTF32, 3-stage cp.async ring -----
#define SA 36
#define SB 136
#define STAGE_A (128*SA)
#define STAGE_B (BK*SB)
#define STAGE_F (STAGE_A + STAGE_B)     // 8960 floats = 35840 B
#define SMEM_FC1 (3*STAGE_F*4)          // 107520 B
__global__ __launch_bounds__(256, 2) void k_fc1(const float* __restrict__ w1) {
    extern __shared__ float sm[];

    int m0 = blockIdx.x * 128, n0 = blockIdx.y * 128;
    int kbase = blockIdx.z * KCHUNK;
    int tid = threadIdx.x, lane = tid & 31, wid = tid >> 5;
    int wm = wid >> 1, wn = wid & 1;
    int ra = lane >> 2, ca = lane & 3;

    float acc[2][8][4];
    #pragma unroll
    for (int i = 0; i < 2; i++)
        #pragma unroll
        for (int j = 0; j < 8; j++)
            #pragma unroll
            for (int q = 0; q < 4; q++) acc[i][j][q] = 0.f;

    int am[4], ak[4], bk[4], bn[4];
    #pragma unroll
    for (int i = 0; i < 4; i++) {
        int c = tid + i*256;
        am[i] = c >> 3;  ak[i] = (c & 7) * 4;
        bk[i] = c >> 5;  bn[i] = (c & 31) * 4;
    }

    uint32_t smA[3], smB[3];
    smA[0] = smem_u32(sm);
    #pragma unroll
    for (int s = 0; s < 3; s++) {
        smA[s] = smA[0] + s*STAGE_F*4;
        smB[s] = smA[s] + STAGE_A*4;
    }

    // prologue: stages 0,1
    #pragma unroll
    for (int s = 0; s < 2; s++) {
        int kc = kbase + s*BK;
        #pragma unroll
        for (int i = 0; i < 4; i++) {
            cp16(smA[s] + (am[i]*SA + ak[i])*4, &g_xo[(size_t)(m0+am[i])*KTOT + kc + ak[i]]);
            cp16(smB[s] + (bk[i]*SB + bn[i])*4, &w1[(size_t)(kc+bk[i])*HID + n0 + bn[i]]);
        }
        asm volatile("cp.async.commit_group;");
    }

    int buf = 0, pre = 2;                 // compute buf, prefetch buf
    for (int it = 0; it < NSTAGE; it++) {
        if (it < NSTAGE-1) asm volatile("cp.async.wait_group 1;");
        else               asm volatile("cp.async.wait_group 0;");
        __syncthreads();                  // all warps done with buf 'pre' (it-1's data)

        if (it + 2 < NSTAGE) {
            int kc = kbase + (it+2)*BK;
            #pragma unroll
            for (int i = 0; i < 4; i++) {
                cp16(smA[pre] + (am[i]*SA + ak[i])*4, &g_xo[(size_t)(m0+am[i])*KTOT + kc + ak[i]]);
                cp16(smB[pre] + (bk[i]*SB + bn[i])*4, &w1[(size_t)(kc+bk[i])*HID + n0 + bn[i]]);
            }
            asm volatile("cp.async.commit_group;");
        }

        const float* As = sm + buf * STAGE_F;
        const float* Bs = As + STAGE_A;

        #pragma unroll
        for (int ks = 0; ks < BK/8; ks++) {
            int k0 = ks*8 + ca;
            uint32_t ah[2][4];
            #pragma unroll
            for (int i = 0; i < 2; i++) {
                int mb = wm*32 + i*16;
                ah[i][0] = __float_as_uint(As[(mb+ra  )*SA + k0  ]);
                ah[i][1] = __float_as_uint(As[(mb+ra+8)*SA + k0  ]);
                ah[i][2] = __float_as_uint(As[(mb+ra  )*SA + k0+4]);
                ah[i][3] = __float_as_uint(As[(mb+ra+8)*SA + k0+4]);
            }
            #pragma unroll
            for (int j = 0; j < 8; j++) {
                int nb = wn*64 + j*8 + ra;
                uint32_t bh[2];
                bh[0] = f2tf32u(Bs[(k0  )*SB + nb]);
                bh[1] = f2tf32u(Bs[(k0+4)*SB + nb]);
                #pragma unroll
                for (int i = 0; i < 2; i++)
                    mma_tf32(acc[i][j], ah[i], bh);
            }
        }
        buf = (buf == 2) ? 0 : buf + 1;
        pre = (pre == 2) ? 0 : pre + 1;
    }

    size_t base = (size_t)blockIdx.z * (ROWS*HID);
    #pragma unroll
    for (int i = 0; i < 2; i++) {
        #pragma unroll
        for (int j = 0; j < 8; j++) {
            int row = m0 + wm*32 + i*16 + ra;
            int col = n0 + wn*64 + j*8 + ca*2;
            *(float2*)&g_Hpart[base + (size_t)row*HID + col]     = make_float2(acc[i][j][0], acc[i][j][1]);
            *(float2*)&g_Hpart[base + (size_t)(row+8)*HID + col] = make_float2(acc[i][j][2], acc[i][j][3]);
        }
    }
}

// ---------------- Kernel E: split-K reduce + leaky_relu + FC2 + transpose --
__global__ void k_fc2(const float* __restrict__ b1, const float* __restrict__ w2,
                      const float* __restrict__ b2, float* __restrict__ out) {
    __shared__ float hrow[HID];
    int row = blockIdx.x;
    int tid = threadIdx.x;          // 256
    for (int i = tid; i < HID; i += 256) {
        float s = 0.f;
        #pragma unroll
        for (int z = 0; z < KSPLIT; z++) s += g_Hpart[(size_t)z*(ROWS*HID) + row*HID + i];
        float v = s + b1[i];
        hrow[i] = v > 0.f ? v : 0.01f * v;
    }
    __syncthreads();
    if (tid < PRED) {
        int b = row >> 5, n = row & 31;
        float acc = b2[tid];
        #pragma unroll 4
        for (int h = 0; h < HID; h++) acc = fmaf(hrow[h], w2[h*PRED + tid], acc);
        out[(b*PRED + tid)*NFch + n] = acc;
    }
}

// ---------------------------------------------------------------------------
extern "C" void kernel_launch(void* const* d_in, const int* in_sizes, int n_in,
                              void* d_out, int out_size) {
    const float* x   = (const float*)d_in[0];
    const float* emb = (const float*)d_in[1];
    const float* br  = (const float*)d_in[8];
    const float* bi  = (const float*)d_in[9];
    const float* w1  = (const float*)d_in[10];
    const float* b1  = (const float*)d_in[11];
    const float* w2  = (const float*)d_in[12];
    const float* b2  = (const float*)d_in[13];
    float* out = (float*)d_out;

    cudaFuncSetAttribute(k_main, cudaFuncAttributeMaxDynamicSharedMemorySize, SMEM_MAIN);
    cudaFuncSetAttribute(k_fc1,  cudaFuncAttributeMaxDynamicSharedMemorySize, SMEM_FC1);

    k_stft<<<ROWS, 128>>>(x);
    k_vred<<<6*WN, 128>>>(emb, (const float*)d_in[2], (const float*)d_in[3],
                          (const float*)d_in[4], (const float*)d_in[5],
                          (const float*)d_in[6], (const float*)d_in[7]);
    k_main<<<ROWS*2, 256, SMEM_MAIN>>>(x, emb, br, bi);
    k_fc1<<<dim3(4, 4, KSPLIT), 256, SMEM_FC1>>>(w1);
    k_fc2<<<ROWS, 256>>>(b1, w2, b2, out);
}

// round 14
// speedup vs baseline: 1.1755x; 1.1755x over previous
#include <cuda_runtime.h>
#include <math.h>
#include <stdint.h>

#define BQ    16
#define SEQ   512
#define NFch  32
#define ECH   128
#define HID   512
#define PRED  96
#define NFFT  64
#define HOPL  32
#define TOPM  32
#define WN    17
#define FB    33
#define LAMB  0.01f

#define ROWS  (BQ*NFch)      // 512  (b*32+n)
#define KTOT  (SEQ*ECH)      // 65536
#define KSPLIT 32
#define KCHUNK (KTOT/KSPLIT) // 2048
#define BK    32
#define NSTAGE (KCHUNK/BK)   // 64
#define EH    64             // e-channels per k_main CTA (e-split)

// ---------------- scratch (static device globals; no runtime alloc) --------
__device__ float2 g_c[ROWS*WN*TOPM];
__device__ int    g_fidx[ROWS*WN*TOPM];
__device__ float  g_v[6*WN*ECH];
__device__ float  g_xo[(size_t)ROWS*KTOT];          // tf32-rounded, ~134MB
__device__ float  g_Hpart[(size_t)KSPLIT*ROWS*HID];

#define TWO_PI 6.28318530717958647692f
#define TWO_PI_D 6.28318530717958647692528676655900577

__device__ __forceinline__ int reflect_t(int j) {
    int t = j - 32;
    if (t < 0) t = -t;
    else if (t > SEQ-1) t = 2*(SEQ-1) - t;
    return t;
}

__device__ __forceinline__ uint32_t f2tf32u(float f) {
    uint32_t r; asm("cvt.rna.tf32.f32 %0, %1;" : "=r"(r) : "f"(f)); return r;
}

__device__ __forceinline__ void mma_tf32(float* c, const uint32_t* a, const uint32_t* b) {
    asm volatile("mma.sync.aligned.m16n8k8.row.col.f32.tf32.tf32.f32 "
        "{%0,%1,%2,%3}, {%4,%5,%6,%7}, {%8,%9}, {%0,%1,%2,%3};"
        : "+f"(c[0]), "+f"(c[1]), "+f"(c[2]), "+f"(c[3])
        : "r"(a[0]), "r"(a[1]), "r"(a[2]), "r"(a[3]), "r"(b[0]), "r"(b[1]));
}

__device__ __forceinline__ uint32_t smem_u32(const void* p) {
    uint32_t a;
    asm("{ .reg .u64 t; cvta.to.shared.u64 t, %1; cvt.u32.u64 %0, t; }" : "=r"(a) : "l"(p));
    return a;
}
__device__ __forceinline__ void cp16(uint32_t dst, const void* src) {
    asm volatile("cp.async.ca.shared.global [%0], [%1], 16;" :: "r"(dst), "l"(src));
}

// packed f32x2 helpers (Blackwell FFMA2; IEEE fp32 per lane)
__device__ __forceinline__ void fma2(unsigned long long& acc, unsigned long long a, unsigned long long b) {
    asm("fma.rn.f32x2 %0, %1, %2, %0;" : "+l"(acc) : "l"(a), "l"(b));
}
__device__ __forceinline__ unsigned long long pack2(float lo, float hi) {
    unsigned long long r; asm("mov.b64 %0, {%1, %2};" : "=l"(r) : "f"(lo), "f"(hi)); return r;
}
__device__ __forceinline__ void unpack2(float& lo, float& hi, unsigned long long v) {
    asm("mov.b64 {%0, %1}, %2;" : "=f"(lo), "=f"(hi) : "l"(v));
}

// ---------------- Kernel A: STFT (df64 fp32, exact twiddles) + top-32 ------
__global__ void k_stft(const float* __restrict__ x) {
    __shared__ float s_s[SEQ];
    __shared__ float win_s[NFFT];
    __shared__ float chi_s[NFFT], clo_s[NFFT];
    __shared__ float mhi_s[NFFT], mlo_s[NFFT];
    __shared__ float Sre[WN*FB], Sim[WN*FB], Sab[WN*FB];
    int blk = blockIdx.x;
    int b = blk >> 5, n = blk & 31;
    int tid = threadIdx.x;          // 128

    for (int t = tid; t < SEQ; t += 128) s_s[t] = x[(b*SEQ + t)*NFch + n];
    for (int t = tid; t < NFFT; t += 128) {
        float a = TWO_PI * (float)t / (float)NFFT;
        win_s[t] = 0.5f - 0.5f * (float)cos((double)a);
        double ad = TWO_PI_D * (double)t / 64.0;
        double cd = cos(ad), msd = -sin(ad);
        float ch = (float)cd;  chi_s[t] = ch; clo_s[t] = (float)(cd - (double)ch);
        float mh = (float)msd; mhi_s[t] = mh; mlo_s[t] = (float)(msd - (double)mh);
    }
    __syncthreads();

    for (int task = tid; task < WN*FB; task += 128) {
        int w = task / FB, f = task % FB;
        float rh = 0.f, rl = 0.f, ih = 0.f, il = 0.f;
        for (int k = 0; k < NFFT; k++) {
            float v = s_s[reflect_t(w*HOPL + k)] * win_s[k];
            int a = (f*k) & 63;
            float ch = chi_s[a];
            float ph = v * ch;
            float pe = fmaf(v, ch, -ph);
            pe = fmaf(v, clo_s[a], pe);
            float s  = rh + ph;
            float bb = s - rh;
            float er = (rh - (s - bb)) + (ph - bb);
            rh = s; rl += er + pe;
            float mh = mhi_s[a];
            float qh = v * mh;
            float qe = fmaf(v, mh, -qh);
            qe = fmaf(v, mlo_s[a], qe);
            float s2  = ih + qh;
            float b2  = s2 - ih;
            float e2  = (ih - (s2 - b2)) + (qh - b2);
            ih = s2; il += e2 + qe;
        }
        float rf = rh + rl, imf = ih + il;
        Sre[task] = rf; Sim[task] = imf;
        Sab[task] = (float)sqrt((double)rf*rf + (double)imf*imf);
    }
    __syncthreads();

    if (tid < WN) {
        int w = tid;
        float mag[FB]; bool used[FB];
        for (int f = 0; f < FB; f++) { mag[f] = Sab[w*FB+f]; used[f] = false; }
        int base = (blk*WN + w) * TOPM;
        for (int m = 0; m < TOPM; m++) {
            int best = 0; float bv = -1.f;
            for (int f = 0; f < FB; f++)
                if (!used[f] && mag[f] > bv) { bv = mag[f]; best = f; }
            used[best] = true;
            g_fidx[base+m] = best;
            g_c[base+m] = make_float2(Sre[w*FB+best], Sim[w*FB+best]);
        }
    }
}

// ---------------- Kernel B: v[k][w][f] = sum_e emb[e]*Wk[w,e,f] ------------
__global__ void k_vred(const float* __restrict__ emb,
                       const float* __restrict__ Wr,  const float* __restrict__ Wi,
                       const float* __restrict__ Wrl, const float* __restrict__ Wil,
                       const float* __restrict__ Wrr, const float* __restrict__ Wir) {
    int k = blockIdx.x / WN, w = blockIdx.x % WN;
    const float* Wm = (k==0)?Wr:(k==1)?Wi:(k==2)?Wrl:(k==3)?Wil:(k==4)?Wrr:Wir;
    int f = threadIdx.x;
    const float* base = Wm + (size_t)w*ECH*ECH + f;
    float acc = 0.f;
    #pragma unroll 4
    for (int e = 0; e < ECH; e++) acc = fmaf(emb[e], base[(size_t)e*ECH], acc);
    g_v[(k*WN + w)*ECH + f] = acc;
}

// ---------------- Kernel C: fused Y + parity irfft + register-carry OLA ----
// The OLA ring is thread-local: the writer of slot (w*32+t+32)&63 at window w
// is the same thread that reads it at window w+1. Carry lives in registers.
// 2 barriers/window, no ring smem, no flush pass, vs loaded from global.
// smem layout (bytes):
//  tw64 ull2[64]    @0     .. 1024
//  y_re float[2048] @1024  .. 9216
//  y_im float[2048] @9216  .. 17408
//  cc   float2[544] @17408 .. 21760
//  win  float[64]   @21760 .. 22016
//  ienv float[32]   @22016 .. 22144
//  emb  float[64]   @22144 .. 22400
//  fidx int[544]    @22400 .. 24576
#define SMEM_MAIN 24576
__global__ __launch_bounds__(256, 4) void k_main(
        const float* __restrict__ x, const float* __restrict__ emb,
        const float* __restrict__ br, const float* __restrict__ bi) {
    extern __shared__ char smraw[];
    ulonglong2* tw64 = (ulonglong2*)(smraw);
    float*  y_re   = (float*) (smraw + 1024);
    float*  y_im   = (float*) (smraw + 9216);
    float2* cc     = (float2*)(smraw + 17408);
    float*  win_s  = (float*) (smraw + 21760);
    float*  ienv   = (float*) (smraw + 22016);
    float*  emb_s  = (float*) (smraw + 22144);
    int*    fidx_s = (int*)   (smraw + 22400);

    int tid = threadIdx.x;          // 256
    int bx  = blockIdx.x;
    int blk = bx >> 1, half = bx & 1;
    int e_off = half * EH;
    int b = blk >> 5, n = blk & 31;

    for (int i = tid; i < 64; i += 256) {
        double ad = TWO_PI_D * (double)i / 64.0;
        float c = (float)cos(ad), s = (float)sin(ad);
        ulonglong2 v; v.x = pack2(c, c); v.y = pack2(-s, -s);
        tw64[i] = v;
    }
    for (int i = tid; i < NFFT; i += 256) {
        float a = TWO_PI * (float)i / (float)NFFT;
        win_s[i] = 0.5f - 0.5f * (float)cos((double)a);
    }
    for (int i = tid; i < HOPL; i += 256) {
        float a = TWO_PI * (float)i / (float)NFFT;
        float c = (float)cos((double)a);
        float w0 = 0.5f - 0.5f*c, w1 = 0.5f + 0.5f*c;
        ienv[i] = 1.0f / (w0*w0 + w1*w1);
    }
    for (int i = tid; i < EH; i += 256) emb_s[i] = emb[e_off + i];
    for (int i = tid; i < WN*TOPM; i += 256) {
        cc[i]     = g_c[blk*WN*TOPM + i];
        fidx_s[i] = g_fidx[blk*WN*TOPM + i];
    }
    __syncthreads();

    int lane = tid & 31, wid = tid >> 5;
    int e0l = (lane & 15) << 2;                 // local e quad (irfft/OLA phase)
    int t0  = wid*4 + ((lane >> 4) << 1);       // base t pair 0..30
    int eY  = tid & 63;                         // Y-phase e (fixed per thread)
    int mY  = tid >> 6;                         // Y-phase base m (0..3)

    float4 carry[2];                            // register OLA ring
    carry[0] = make_float4(0.f,0.f,0.f,0.f);
    carry[1] = make_float4(0.f,0.f,0.f,0.f);

    for (int w = 0; w < WN; w++) {
        // ---- Y phase: weights straight from global (e fixed per thread) ----
        float vr  = g_v[(0*WN + w)*ECH + e_off + eY];
        float vi  = g_v[(1*WN + w)*ECH + e_off + eY];
        float vrl = g_v[(2*WN + w)*ECH + e_off + eY];
        float vil = g_v[(3*WN + w)*ECH + e_off + eY];
        float vrr = g_v[(4*WN + w)*ECH + e_off + eY];
        float vir = g_v[(5*WN + w)*ECH + e_off + eY];
        float brv = br[w*ECH + e_off + eY];
        float biv = bi[w*ECH + e_off + eY];

        #pragma unroll
        for (int j = 0; j < 8; j++) {
            int m = mY + 4*j;
            float2 c0 = cc[w*TOPM + m];
            float2 cl = (w > 0)    ? cc[(w-1)*TOPM + m] : make_float2(0.f,0.f);
            float2 cr = (w < WN-1) ? cc[(w+1)*TOPM + m] : make_float2(0.f,0.f);
            float ore = c0.x*vr - c0.y*vi + cl.x*vrl - cl.y*vil + cr.x*vrr - cr.y*vir + brv;
            float oim = c0.y*vr + c0.x*vi + cl.y*vrl + cl.x*vil + cr.y*vrr + cr.x*vir + biv;
            float yre = fmaxf(fmaxf(ore, 0.f) - LAMB, 0.f);
            float yim = fmaxf(fmaxf(oim, 0.f) - LAMB, 0.f);
            int f = fidx_s[w*TOPM + m];
            if (f == 0 || f == FB-1) {
                y_re[m*EH + eY] = yre * 0.015625f;
                y_im[m*EH + eY] = 0.f;
            } else {
                y_re[m*EH + eY] = yre * 0.03125f;
                y_im[m*EH + eY] = yim * 0.03125f;
            }
        }
        __syncthreads();

        // ---- irfft phase: parity-split over 32 top-k bins ----
        unsigned long long aE[2][2], aO[2][2];
        #pragma unroll
        for (int kk = 0; kk < 2; kk++) {
            aE[kk][0] = aE[kk][1] = 0ull;
            aO[kk][0] = aO[kk][1] = 0ull;
        }

        #pragma unroll 4
        for (int m = 0; m < TOPM; m++) {
            int f = fidx_s[w*TOPM + m];
            ulonglong2 yr = *(const ulonglong2*)&y_re[m*EH + e0l];
            ulonglong2 yi = *(const ulonglong2*)&y_im[m*EH + e0l];
            int ft = f * t0;
            ulonglong2 cs0 = tw64[ft & 63];
            ulonglong2 cs1 = tw64[(ft + f) & 63];
            if (f & 1) {
                fma2(aO[0][0], yr.x, cs0.x); fma2(aO[0][0], yi.x, cs0.y);
                fma2(aO[0][1], yr.y, cs0.x); fma2(aO[0][1], yi.y, cs0.y);
                fma2(aO[1][0], yr.x, cs1.x); fma2(aO[1][0], yi.x, cs1.y);
                fma2(aO[1][1], yr.y, cs1.x); fma2(aO[1][1], yi.y, cs1.y);
            } else {
                fma2(aE[0][0], yr.x, cs0.x); fma2(aE[0][0], yi.x, cs0.y);
                fma2(aE[0][1], yr.y, cs0.x); fma2(aE[0][1], yi.y, cs0.y);
                fma2(aE[1][0], yr.x, cs1.x); fma2(aE[1][0], yi.x, cs1.y);
                fma2(aE[1][1], yr.y, cs1.x); fma2(aE[1][1], yi.y, cs1.y);
            }
        }

        // ---- combine + register-carry OLA + output ----
        #pragma unroll
        for (int kk = 0; kk < 2; kk++) {
            int t  = t0 + kk;
            int tm = t + 32;
            float pe0, pe1, pe2, pe3, po0, po1, po2, po3;
            unpack2(pe0, pe1, aE[kk][0]); unpack2(pe2, pe3, aE[kk][1]);
            unpack2(po0, po1, aO[kk][0]); unpack2(po2, po3, aO[kk][1]);

            float wt = win_s[t], wmr = win_s[tm];
            float4 vt, vm;
            vt.x = (pe0+po0)*wt;  vt.y = (pe1+po1)*wt;
            vt.z = (pe2+po2)*wt;  vt.w = (pe3+po3)*wt;
            vm.x = (pe0-po0)*wmr; vm.y = (pe1-po1)*wmr;
            vm.z = (pe2-po2)*wmr; vm.w = (pe3-po3)*wmr;

            if (w > 0) {
                float4 s4;
                s4.x = vt.x + carry[kk].x; s4.y = vt.y + carry[kk].y;
                s4.z = vt.z + carry[kk].z; s4.w = vt.w + carry[kk].w;
                int t_out = (w-1)*HOPL + t;
                float iv = ienv[t];
                float xv = x[(b*SEQ + t_out)*NFch + n];
                uint4 o;
                o.x = f2tf32u(s4.x * iv + xv * emb_s[e0l+0]);
                o.y = f2tf32u(s4.y * iv + xv * emb_s[e0l+1]);
                o.z = f2tf32u(s4.z * iv + xv * emb_s[e0l+2]);
                o.w = f2tf32u(s4.w * iv + xv * emb_s[e0l+3]);
                *(uint4*)&g_xo[(size_t)blk*KTOT + t_out*ECH + e_off + e0l] = o;
            }
            carry[kk] = vm;
        }
        __syncthreads();
    }
}

// ---------------- Kernel D: FC1 split-K, 1xTF32, 2-stage cp.async (R12) ----
#define SA 36
#define SB 136
#define STAGE_A (128*SA)
#define STAGE_B (BK*SB)
#define STAGE_F (STAGE_A + STAGE_B)     // 8960 floats = 35840 B
#define SMEM_FC1 (2*STAGE_F*4)          // 71680 B
__global__ __launch_bounds__(256, 2) void k_fc1(const float* __restrict__ w1) {
    extern __shared__ float sm[];

    int m0 = blockIdx.x * 128, n0 = blockIdx.y * 128;
    int kbase = blockIdx.z * KCHUNK;
    int tid = threadIdx.x, lane = tid & 31, wid = tid >> 5;
    int wm = wid >> 1, wn = wid & 1;
    int ra = lane >> 2, ca = lane & 3;

    float acc[2][8][4];
    #pragma unroll
    for (int i = 0; i < 2; i++)
        #pragma unroll
        for (int j = 0; j < 8; j++)
            #pragma unroll
            for (int q = 0; q < 4; q++) acc[i][j][q] = 0.f;

    int am[4], ak[4], bk[4], bn[4];
    #pragma unroll
    for (int i = 0; i < 4; i++) {
        int c = tid + i*256;
        am[i] = c >> 3;  ak[i] = (c & 7) * 4;
        bk[i] = c >> 5;  bn[i] = (c & 31) * 4;
    }

    uint32_t smA[2], smB[2];
    smA[0] = smem_u32(sm);
    smB[0] = smA[0] + STAGE_A*4;
    smA[1] = smA[0] + STAGE_F*4;
    smB[1] = smB[0] + STAGE_F*4;

    {
        int kc = kbase;
        #pragma unroll
        for (int i = 0; i < 4; i++) {
            cp16(smA[0] + (am[i]*SA + ak[i])*4, &g_xo[(size_t)(m0+am[i])*KTOT + kc + ak[i]]);
            cp16(smB[0] + (bk[i]*SB + bn[i])*4, &w1[(size_t)(kc+bk[i])*HID + n0 + bn[i]]);
        }
        asm volatile("cp.async.commit_group;");
    }

    for (int it = 0; it < NSTAGE; it++) {
        if (it + 1 < NSTAGE) {
            int buf = (it+1) & 1;
            int kc = kbase + (it+1)*BK;
            #pragma unroll
            for (int i = 0; i < 4; i++) {
                cp16(smA[buf] + (am[i]*SA + ak[i])*4, &g_xo[(size_t)(m0+am[i])*KTOT + kc + ak[i]]);
                cp16(smB[buf] + (bk[i]*SB + bn[i])*4, &w1[(size_t)(kc+bk[i])*HID + n0 + bn[i]]);
            }
            asm volatile("cp.async.commit_group;");
            asm volatile("cp.async.wait_group 1;");
        } else {
            asm volatile("cp.async.wait_group 0;");
        }
        __syncthreads();

        const float* As = sm + (it & 1) * STAGE_F;
        const float* Bs = As + STAGE_A;

        #pragma unroll
        for (int ks = 0; ks < BK/8; ks++) {
            int k0 = ks*8 + ca;
            uint32_t ah[2][4];
            #pragma unroll
            for (int i = 0; i < 2; i++) {
                int mb = wm*32 + i*16;
                ah[i][0] = __float_as_uint(As[(mb+ra  )*SA + k0  ]);
                ah[i][1] = __float_as_uint(As[(mb+ra+8)*SA + k0  ]);
                ah[i][2] = __float_as_uint(As[(mb+ra  )*SA + k0+4]);
                ah[i][3] = __float_as_uint(As[(mb+ra+8)*SA + k0+4]);
            }
            #pragma unroll
            for (int j = 0; j < 8; j++) {
                int nb = wn*64 + j*8 + ra;
                uint32_t bh[2];
                bh[0] = f2tf32u(Bs[(k0  )*SB + nb]);
                bh[1] = f2tf32u(Bs[(k0+4)*SB + nb]);
                #pragma unroll
                for (int i = 0; i < 2; i++)
                    mma_tf32(acc[i][j], ah[i], bh);
            }
        }
        __syncthreads();
    }

    size_t base = (size_t)blockIdx.z * (ROWS*HID);
    #pragma unroll
    for (int i = 0; i < 2; i++) {
        #pragma unroll
        for (int j = 0; j < 8; j++) {
            int row = m0 + wm*32 + i*16 + ra;
            int col = n0 + wn*64 + j*8 + ca*2;
            *(float2*)&g_Hpart[base + (size_t)row*HID + col]     = make_float2(acc[i][j][0], acc[i][j][1]);
            *(float2*)&g_Hpart[base + (size_t)(row+8)*HID + col] = make_float2(acc[i][j][2], acc[i][j][3]);
        }
    }
}

// ---------------- Kernel E: split-K reduce + leaky_relu + FC2 + transpose --
__global__ void k_fc2(const float* __restrict__ b1, const float* __restrict__ w2,
                      const float* __restrict__ b2, float* __restrict__ out) {
    __shared__ float hrow[HID];
    int row = blockIdx.x;
    int tid = threadIdx.x;          // 256
    for (int i = tid; i < HID; i += 256) {
        float s = 0.f;
        #pragma unroll
        for (int z = 0; z < KSPLIT; z++) s += g_Hpart[(size_t)z*(ROWS*HID) + row*HID + i];
        float v = s + b1[i];
        hrow[i] = v > 0.f ? v : 0.01f * v;
    }
    __syncthreads();
    if (tid < PRED) {
        int b = row >> 5, n = row & 31;
        float acc = b2[tid];
        #pragma unroll 4
        for (int h = 0; h < HID; h++) acc = fmaf(hrow[h], w2[h*PRED + tid], acc);
        out[(b*PRED + tid)*NFch + n] = acc;
    }
}

// ---------------------------------------------------------------------------
extern "C" void kernel_launch(void* const* d_in, const int* in_sizes, int n_in,
                              void* d_out, int out_size) {
    const float* x   = (const float*)d_in[0];
    const float* emb = (const float*)d_in[1];
    const float* br  = (const float*)d_in[8];
    const float* bi  = (const float*)d_in[9];
    const float* w1  = (const float*)d_in[10];
    const float* b1  = (const float*)d_in[11];
    const float* w2  = (const float*)d_in[12];
    const float* b2  = (const float*)d_in[13];
    float* out = (float*)d_out;

    cudaFuncSetAttribute(k_main, cudaFuncAttributeMaxDynamicSharedMemorySize, SMEM_MAIN);
    cudaFuncSetAttribute(k_fc1,  cudaFuncAttributeMaxDynamicSharedMemorySize, SMEM_FC1);

    k_stft<<<ROWS, 128>>>(x);
    k_vred<<<6*WN, 128>>>(emb, (const float*)d_in[2], (const float*)d_in[3],
                          (const float*)d_in[4], (const float*)d_in[5],
                          (const float*)d_in[6], (const float*)d_in[7]);
    k_main<<<ROWS*2, 256, SMEM_MAIN>>>(x, emb, br, bi);
    k_fc1<<<dim3(4, 4, KSPLIT), 256, SMEM_FC1>>>(w1);
    k_fc2<<<ROWS, 256>>>(b1, w2, b2, out);
}

// round 16
// speedup vs baseline: 1.3024x; 1.1080x over previous
#include <cuda_runtime.h>
#include <cuda_fp16.h>
#include <math.h>
#include <stdint.h>

#define BQ    16
#define SEQ   512
#define NFch  32
#define ECH   128
#define HID   512
#define PRED  96
#define NFFT  64
#define HOPL  32
#define TOPM  32
#define WN    17
#define FB    33
#define LAMB  0.01f

#define ROWS  (BQ*NFch)      // 512
#define KTOT  (SEQ*ECH)      // 65536
#define KSPLIT 32
#define KCHUNK (KTOT/KSPLIT) // 2048
#define BK    32
#define NSTAGE (KCHUNK/BK)   // 64
#define EH    64

// ---------------- scratch (static device globals; no runtime alloc) --------
__device__ float2 g_c[ROWS*WN*TOPM];
__device__ int    g_fidx[ROWS*WN*TOPM];
__device__ float  g_v[6*WN*ECH];
__device__ __half g_xo[(size_t)ROWS*KTOT];          // fp16, ~67MB
__device__ __half g_w1t[(size_t)HID*KTOT];          // w1^T, fp16, ~67MB
__device__ float  g_Hpart[(size_t)KSPLIT*ROWS*HID];

#define TWO_PI 6.28318530717958647692f
#define TWO_PI_D 6.28318530717958647692528676655900577

__device__ __forceinline__ int reflect_t(int j) {
    int t = j - 32;
    if (t < 0) t = -t;
    else if (t > SEQ-1) t = 2*(SEQ-1) - t;
    return t;
}

__device__ __forceinline__ uint32_t smem_u32(const void* p) {
    uint32_t a;
    asm("{ .reg .u64 t; cvta.to.shared.u64 t, %1; cvt.u32.u64 %0, t; }" : "=r"(a) : "l"(p));
    return a;
}
__device__ __forceinline__ void cp16(uint32_t dst, const void* src) {
    asm volatile("cp.async.ca.shared.global [%0], [%1], 16;" :: "r"(dst), "l"(src));
}

// packed f32x2 helpers (Blackwell FFMA2; IEEE fp32 per lane)
__device__ __forceinline__ void fma2(unsigned long long& acc, unsigned long long a, unsigned long long b) {
    asm("fma.rn.f32x2 %0, %1, %2, %0;" : "+l"(acc) : "l"(a), "l"(b));
}
__device__ __forceinline__ unsigned long long pack2(float lo, float hi) {
    unsigned long long r; asm("mov.b64 %0, {%1, %2};" : "=l"(r) : "f"(lo), "f"(hi)); return r;
}
__device__ __forceinline__ void unpack2(float& lo, float& hi, unsigned long long v) {
    asm("mov.b64 {%0, %1}, %2;" : "=f"(lo), "=f"(hi) : "l"(v));
}

__device__ __forceinline__ void mma_f16(float* c, const uint32_t* a, uint32_t b0, uint32_t b1) {
    asm volatile("mma.sync.aligned.m16n8k16.row.col.f32.f16.f16.f32 "
        "{%0,%1,%2,%3}, {%4,%5,%6,%7}, {%8,%9}, {%0,%1,%2,%3};"
        : "+f"(c[0]), "+f"(c[1]), "+f"(c[2]), "+f"(c[3])
        : "r"(a[0]), "r"(a[1]), "r"(a[2]), "r"(a[3]), "r"(b0), "r"(b1));
}

// ---------------- Kernel A: STFT (df64 fp32, exact twiddles) + top-32 ------
__global__ void k_stft(const float* __restrict__ x) {
    __shared__ float s_s[SEQ];
    __shared__ float win_s[NFFT];
    __shared__ float chi_s[NFFT], clo_s[NFFT];
    __shared__ float mhi_s[NFFT], mlo_s[NFFT];
    __shared__ float Sre[WN*FB], Sim[WN*FB], Sab[WN*FB];
    int blk = blockIdx.x;
    int b = blk >> 5, n = blk & 31;
    int tid = threadIdx.x;          // 128

    for (int t = tid; t < SEQ; t += 128) s_s[t] = x[(b*SEQ + t)*NFch + n];
    for (int t = tid; t < NFFT; t += 128) {
        float a = TWO_PI * (float)t / (float)NFFT;
        win_s[t] = 0.5f - 0.5f * (float)cos((double)a);
        double ad = TWO_PI_D * (double)t / 64.0;
        double cd = cos(ad), msd = -sin(ad);
        float ch = (float)cd;  chi_s[t] = ch; clo_s[t] = (float)(cd - (double)ch);
        float mh = (float)msd; mhi_s[t] = mh; mlo_s[t] = (float)(msd - (double)mh);
    }
    __syncthreads();

    for (int task = tid; task < WN*FB; task += 128) {
        int w = task / FB, f = task % FB;
        float rh = 0.f, rl = 0.f, ih = 0.f, il = 0.f;
        for (int k = 0; k < NFFT; k++) {
            float v = s_s[reflect_t(w*HOPL + k)] * win_s[k];
            int a = (f*k) & 63;
            float ch = chi_s[a];
            float ph = v * ch;
            float pe = fmaf(v, ch, -ph);
            pe = fmaf(v, clo_s[a], pe);
            float s  = rh + ph;
            float bb = s - rh;
            float er = (rh - (s - bb)) + (ph - bb);
            rh = s; rl += er + pe;
            float mh = mhi_s[a];
            float qh = v * mh;
            float qe = fmaf(v, mh, -qh);
            qe = fmaf(v, mlo_s[a], qe);
            float s2  = ih + qh;
            float b2  = s2 - ih;
            float e2  = (ih - (s2 - b2)) + (qh - b2);
            ih = s2; il += e2 + qe;
        }
        float rf = rh + rl, imf = ih + il;
        Sre[task] = rf; Sim[task] = imf;
        Sab[task] = (float)sqrt((double)rf*rf + (double)imf*imf);
    }
    __syncthreads();

    if (tid < WN) {
        int w = tid;
        float mag[FB]; bool used[FB];
        for (int f = 0; f < FB; f++) { mag[f] = Sab[w*FB+f]; used[f] = false; }
        int base = (blk*WN + w) * TOPM;
        for (int m = 0; m < TOPM; m++) {
            int best = 0; float bv = -1.f;
            for (int f = 0; f < FB; f++)
                if (!used[f] && mag[f] > bv) { bv = mag[f]; best = f; }
            used[best] = true;
            g_fidx[base+m] = best;
            g_c[base+m] = make_float2(Sre[w*FB+best], Sim[w*FB+best]);
        }
    }
}

// ---------------- Kernel B: v[k][w][f] = sum_e emb[e]*Wk[w,e,f] ------------
__global__ void k_vred(const float* __restrict__ emb,
                       const float* __restrict__ Wr,  const float* __restrict__ Wi,
                       const float* __restrict__ Wrl, const float* __restrict__ Wil,
                       const float* __restrict__ Wrr, const float* __restrict__ Wir) {
    int k = blockIdx.x / WN, w = blockIdx.x % WN;
    const float* Wm = (k==0)?Wr:(k==1)?Wi:(k==2)?Wrl:(k==3)?Wil:(k==4)?Wrr:Wir;
    int f = threadIdx.x;
    const float* base = Wm + (size_t)w*ECH*ECH + f;
    float acc = 0.f;
    #pragma unroll 4
    for (int e = 0; e < ECH; e++) acc = fmaf(emb[e], base[(size_t)e*ECH], acc);
    g_v[(k*WN + w)*ECH + f] = acc;
}

// ---------------- Kernel B2: w1 transpose + fp16 round ---------------------
__global__ void k_wt(const float* __restrict__ w1) {
    __shared__ float t[32][33];
    int kt = blockIdx.x, nt = blockIdx.y;
    int x = threadIdx.x & 31, y4 = threadIdx.x >> 5;   // 256 threads
    #pragma unroll
    for (int j = 0; j < 4; j++) {
        int row = y4*4 + j;
        t[row][x] = w1[(size_t)(kt*32 + row)*HID + nt*32 + x];
    }
    __syncthreads();
    #pragma unroll
    for (int j = 0; j < 4; j++) {
        int row = y4*4 + j;
        g_w1t[(size_t)(nt*32 + row)*KTOT + kt*32 + x] = __float2half_rn(t[x][row]);
    }
}

// ---------------- Kernel C: fused Y + parity irfft + register-carry OLA ----
#define SMEM_MAIN 24576
__global__ __launch_bounds__(256, 4) void k_main(
        const float* __restrict__ x, const float* __restrict__ emb,
        const float* __restrict__ br, const float* __restrict__ bi) {
    extern __shared__ char smraw[];
    ulonglong2* tw64 = (ulonglong2*)(smraw);
    float*  y_re   = (float*) (smraw + 1024);
    float*  y_im   = (float*) (smraw + 9216);
    float2* cc     = (float2*)(smraw + 17408);
    float*  win_s  = (float*) (smraw + 21760);
    float*  ienv   = (float*) (smraw + 22016);
    float*  emb_s  = (float*) (smraw + 22144);
    int*    fidx_s = (int*)   (smraw + 22400);

    int tid = threadIdx.x;          // 256
    int bx  = blockIdx.x;
    int blk = bx >> 1, half = bx & 1;
    int e_off = half * EH;
    int b = blk >> 5, n = blk & 31;

    for (int i = tid; i < 64; i += 256) {
        double ad = TWO_PI_D * (double)i / 64.0;
        float c = (float)cos(ad), s = (float)sin(ad);
        ulonglong2 v; v.x = pack2(c, c); v.y = pack2(-s, -s);
        tw64[i] = v;
    }
    for (int i = tid; i < NFFT; i += 256) {
        float a = TWO_PI * (float)i / (float)NFFT;
        win_s[i] = 0.5f - 0.5f * (float)cos((double)a);
    }
    for (int i = tid; i < HOPL; i += 256) {
        float a = TWO_PI * (float)i / (float)NFFT;
        float c = (float)cos((double)a);
        float w0 = 0.5f - 0.5f*c, w1v = 0.5f + 0.5f*c;
        ienv[i] = 1.0f / (w0*w0 + w1v*w1v);
    }
    for (int i = tid; i < EH; i += 256) emb_s[i] = emb[e_off + i];
    for (int i = tid; i < WN*TOPM; i += 256) {
        cc[i]     = g_c[blk*WN*TOPM + i];
        fidx_s[i] = g_fidx[blk*WN*TOPM + i];
    }
    __syncthreads();

    int lane = tid & 31, wid = tid >> 5;
    int e0l = (lane & 15) << 2;
    int t0  = wid*4 + ((lane >> 4) << 1);
    int eY  = tid & 63;
    int mY  = tid >> 6;

    float4 carry[2];
    carry[0] = make_float4(0.f,0.f,0.f,0.f);
    carry[1] = make_float4(0.f,0.f,0.f,0.f);

    for (int w = 0; w < WN; w++) {
        float vr  = g_v[(0*WN + w)*ECH + e_off + eY];
        float vi  = g_v[(1*WN + w)*ECH + e_off + eY];
        float vrl = g_v[(2*WN + w)*ECH + e_off + eY];
        float vil = g_v[(3*WN + w)*ECH + e_off + eY];
        float vrr = g_v[(4*WN + w)*ECH + e_off + eY];
        float vir = g_v[(5*WN + w)*ECH + e_off + eY];
        float brv = br[w*ECH + e_off + eY];
        float biv = bi[w*ECH + e_off + eY];

        #pragma unroll
        for (int j = 0; j < 8; j++) {
            int m = mY + 4*j;
            float2 c0 = cc[w*TOPM + m];
            float2 cl = (w > 0)    ? cc[(w-1)*TOPM + m] : make_float2(0.f,0.f);
            float2 cr = (w < WN-1) ? cc[(w+1)*TOPM + m] : make_float2(0.f,0.f);
            float ore = c0.x*vr - c0.y*vi + cl.x*vrl - cl.y*vil + cr.x*vrr - cr.y*vir + brv;
            float oim = c0.y*vr + c0.x*vi + cl.y*vrl + cl.x*vil + cr.y*vrr + cr.x*vir + biv;
            float yre = fmaxf(fmaxf(ore, 0.f) - LAMB, 0.f);
            float yim = fmaxf(fmaxf(oim, 0.f) - LAMB, 0.f);
            int f = fidx_s[w*TOPM + m];
            if (f == 0 || f == FB-1) {
                y_re[m*EH + eY] = yre * 0.015625f;
                y_im[m*EH + eY] = 0.f;
            } else {
                y_re[m*EH + eY] = yre * 0.03125f;
                y_im[m*EH + eY] = yim * 0.03125f;
            }
        }
        __syncthreads();

        unsigned long long aE[2][2], aO[2][2];
        #pragma unroll
        for (int kk = 0; kk < 2; kk++) {
            aE[kk][0] = aE[kk][1] = 0ull;
            aO[kk][0] = aO[kk][1] = 0ull;
        }

        #pragma unroll 4
        for (int m = 0; m < TOPM; m++) {
            int f = fidx_s[w*TOPM + m];
            ulonglong2 yr = *(const ulonglong2*)&y_re[m*EH + e0l];
            ulonglong2 yi = *(const ulonglong2*)&y_im[m*EH + e0l];
            int ft = f * t0;
            ulonglong2 cs0 = tw64[ft & 63];
            ulonglong2 cs1 = tw64[(ft + f) & 63];
            if (f & 1) {
                fma2(aO[0][0], yr.x, cs0.x); fma2(aO[0][0], yi.x, cs0.y);
                fma2(aO[0][1], yr.y, cs0.x); fma2(aO[0][1], yi.y, cs0.y);
                fma2(aO[1][0], yr.x, cs1.x); fma2(aO[1][0], yi.x, cs1.y);
                fma2(aO[1][1], yr.y, cs1.x); fma2(aO[1][1], yi.y, cs1.y);
            } else {
                fma2(aE[0][0], yr.x, cs0.x); fma2(aE[0][0], yi.x, cs0.y);
                fma2(aE[0][1], yr.y, cs0.x); fma2(aE[0][1], yi.y, cs0.y);
                fma2(aE[1][0], yr.x, cs1.x); fma2(aE[1][0], yi.x, cs1.y);
                fma2(aE[1][1], yr.y, cs1.x); fma2(aE[1][1], yi.y, cs1.y);
            }
        }

        #pragma unroll
        for (int kk = 0; kk < 2; kk++) {
            int t  = t0 + kk;
            int tm = t + 32;
            float pe0, pe1, pe2, pe3, po0, po1, po2, po3;
            unpack2(pe0, pe1, aE[kk][0]); unpack2(pe2, pe3, aE[kk][1]);
            unpack2(po0, po1, aO[kk][0]); unpack2(po2, po3, aO[kk][1]);

            float wt = win_s[t], wmr = win_s[tm];
            float4 vt, vm;
            vt.x = (pe0+po0)*wt;  vt.y = (pe1+po1)*wt;
            vt.z = (pe2+po2)*wt;  vt.w = (pe3+po3)*wt;
            vm.x = (pe0-po0)*wmr; vm.y = (pe1-po1)*wmr;
            vm.z = (pe2-po2)*wmr; vm.w = (pe3-po3)*wmr;

            if (w > 0) {
                float4 s4;
                s4.x = vt.x + carry[kk].x; s4.y = vt.y + carry[kk].y;
                s4.z = vt.z + carry[kk].z; s4.w = vt.w + carry[kk].w;
                int t_out = (w-1)*HOPL + t;
                float iv = ienv[t];
                float xv = x[(b*SEQ + t_out)*NFch + n];
                __half2 h0 = __floats2half2_rn(s4.x * iv + xv * emb_s[e0l+0],
                                               s4.y * iv + xv * emb_s[e0l+1]);
                __half2 h1 = __floats2half2_rn(s4.z * iv + xv * emb_s[e0l+2],
                                               s4.w * iv + xv * emb_s[e0l+3]);
                uint2 o;
                o.x = *(uint32_t*)&h0;
                o.y = *(uint32_t*)&h1;
                *(uint2*)&g_xo[(size_t)blk*KTOT + t_out*ECH + e_off + e0l] = o;
            }
            carry[kk] = vm;
        }
        __syncthreads();
    }
}

// ---------------- Kernel D: FC1 split-K, fp16 m16n8k16 tensor GEMM ---------
// smem: 2 stages x (A 16KB + B 16KB) = 64KB. 128B rows (32 halves data),
// 16B-chunk XOR swizzle q^=r&7 -> provably conflict-free fragment loads.
#define FC1_SMEM 65536
__global__ __launch_bounds__(256, 2) void k_fc1() {
    extern __shared__ char smc[];
    uint32_t sb = smem_u32(smc);

    int m0 = blockIdx.x * 128, n0 = blockIdx.y * 128;
    int kbase = blockIdx.z * KCHUNK;
    int tid = threadIdx.x, lane = tid & 31, wid = tid >> 5;
    int wm = wid >> 1, wn = wid & 1;          // warp tile: 32(M) x 64(N)
    int ra = lane >> 2, ca = lane & 3;

    float acc[2][8][4];
    #pragma unroll
    for (int i = 0; i < 2; i++)
        #pragma unroll
        for (int j = 0; j < 8; j++)
            #pragma unroll
            for (int q = 0; q < 4; q++) acc[i][j][q] = 0.f;

    // cp.async coords: 512 chunks per tile (128 rows x 4), 2 per thread each
    int cr[2], cq[2], cdst[2];
    #pragma unroll
    for (int i = 0; i < 2; i++) {
        int c = tid + i*256;
        cr[i] = c >> 2; cq[i] = c & 3;
        cdst[i] = cr[i]*128 + ((cq[i] ^ (cr[i] & 7)) << 4);
    }

    #define LOAD_STAGE(s, bsel) do {                                          \
        int kc_ = kbase + (s)*BK;                                             \
        _Pragma("unroll")                                                     \
        for (int i_ = 0; i_ < 2; i_++) {                                      \
            cp16(sb + (bsel)*32768 + cdst[i_],                                \
                 &g_xo[(size_t)(m0+cr[i_])*KTOT + kc_ + cq[i_]*8]);           \
            cp16(sb + (bsel)*32768 + 16384 + cdst[i_],                        \
                 &g_w1t[(size_t)(n0+cr[i_])*KTOT + kc_ + cq[i_]*8]);          \
        }                                                                     \
        asm volatile("cp.async.commit_group;");                               \
    } while (0)

    LOAD_STAGE(0, 0);

    for (int it = 0; it < NSTAGE; it++) {
        if (it + 1 < NSTAGE) {
            LOAD_STAGE(it + 1, (it + 1) & 1);
            asm volatile("cp.async.wait_group 1;");
        } else {
            asm volatile("cp.async.wait_group 0;");
        }
        __syncthreads();

        const char* As = smc + (it & 1) * 32768;
        const char* Bs = As + 16384;
        int woff = ca * 4;

        #pragma unroll
        for (int ks = 0; ks < 2; ks++) {
            int kq = ks * 2;
            int c0off = ((kq ^ ra) << 4) + woff;
            int c1off = (((kq + 1) ^ ra) << 4) + woff;
            uint32_t a[2][4];
            #pragma unroll
            for (int i = 0; i < 2; i++) {
                int mb = wm*32 + i*16;
                a[i][0] = *(const uint32_t*)(As + (mb+ra  )*128 + c0off);
                a[i][1] = *(const uint32_t*)(As + (mb+ra+8)*128 + c0off);
                a[i][2] = *(const uint32_t*)(As + (mb+ra  )*128 + c1off);
                a[i][3] = *(const uint32_t*)(As + (mb+ra+8)*128 + c1off);
            }
            #pragma unroll
            for (int j = 0; j < 8; j++) {
                int nb = wn*64 + j*8 + ra;
                uint32_t b0 = *(const uint32_t*)(Bs + nb*128 + c0off);
                uint32_t b1 = *(const uint32_t*)(Bs + nb*128 + c1off);
                #pragma unroll
                for (int i = 0; i < 2; i++)
                    mma_f16(acc[i][j], a[i], b0, b1);
            }
        }
        __syncthreads();
    }

    size_t base = (size_t)blockIdx.z * (ROWS*HID);
    #pragma unroll
    for (int i = 0; i < 2; i++) {
        #pragma unroll
        for (int j = 0; j < 8; j++) {
            int row = m0 + wm*32 + i*16 + ra;
            int col = n0 + wn*64 + j*8 + ca*2;
            *(float2*)&g_Hpart[base + (size_t)row*HID + col]     = make_float2(acc[i][j][0], acc[i][j][1]);
            *(float2*)&g_Hpart[base + (size_t)(row+8)*HID + col] = make_float2(acc[i][j][2], acc[i][j][3]);
        }
    }
}

// ---------------- Kernel E: split-K reduce + leaky_relu + FC2 + transpose --
__global__ void k_fc2(const float* __restrict__ b1, const float* __restrict__ w2,
                      const float* __restrict__ b2, float* __restrict__ out) {
    __shared__ float hrow[HID];
    int row = blockIdx.x;
    int tid = threadIdx.x;          // 256
    for (int i = tid; i < HID; i += 256) {
        float s = 0.f;
        #pragma unroll
        for (int z = 0; z < KSPLIT; z++) s += g_Hpart[(size_t)z*(ROWS*HID) + row*HID + i];
        float v = s + b1[i];
        hrow[i] = v > 0.f ? v : 0.01f * v;
    }
    __syncthreads();
    if (tid < PRED) {
        int b = row >> 5, n = row & 31;
        float acc = b2[tid];
        #pragma unroll 4
        for (int h = 0; h < HID; h++) acc = fmaf(hrow[h], w2[h*PRED + tid], acc);
        out[(b*PRED + tid)*NFch + n] = acc;
    }
}

// ---------------------------------------------------------------------------
extern "C" void kernel_launch(void* const* d_in, const int* in_sizes, int n_in,
                              void* d_out, int out_size) {
    const float* x   = (const float*)d_in[0];
    const float* emb = (const float*)d_in[1];
    const float* br  = (const float*)d_in[8];
    const float* bi  = (const float*)d_in[9];
    const float* w1  = (const float*)d_in[10];
    const float* b1  = (const float*)d_in[11];
    const float* w2  = (const float*)d_in[12];
    const float* b2  = (const float*)d_in[13];
    float* out = (float*)d_out;

    cudaFuncSetAttribute(k_main, cudaFuncAttributeMaxDynamicSharedMemorySize, SMEM_MAIN);
    cudaFuncSetAttribute(k_fc1,  cudaFuncAttributeMaxDynamicSharedMemorySize, FC1_SMEM);

    k_wt<<<dim3(KTOT/32, HID/32), 256>>>(w1);
    k_stft<<<ROWS, 128>>>(x);
    k_vred<<<6*WN, 128>>>(emb, (const float*)d_in[2], (const float*)d_in[3],
                          (const float*)d_in[4], (const float*)d_in[5],
                          (const float*)d_in[6], (const float*)d_in[7]);
    k_main<<<ROWS*2, 256, SMEM_MAIN>>>(x, emb, br, bi);
    k_fc1<<<dim3(4, 4, KSPLIT), 256, FC1_SMEM>>>();
    k_fc2<<<ROWS, 256>>>(b1, w2, b2, out);
}